// round 8
// baseline (speedup 1.0000x reference)
#include <cuda_runtime.h>

#define LMAX 32768
#define NMAX 32768
#define GRIDC 32
#define NCELL (GRIDC * GRIDC * GRIDC)
#define CELLW 16.0f
#define GORIG (-256.0f)

#define POSINF __int_as_float(0x7F800000)

typedef unsigned long long ull;

// ---------------- device scratch (no allocations allowed) ----------------
__device__ unsigned int  g_keys[LMAX];
__device__ unsigned char g_islm[LMAX];
__device__ float         g_thr;
__device__ int           g_count;
__device__ int           g_ecount;
__device__ float4        g_candC[LMAX];      // kept cand: x,y,z, idx-as-floatbits
__device__ int           g_candIdx[LMAX];    // compacted kept -> original index
__device__ unsigned      g_ccnt[NCELL];      // candidate grid counts
__device__ unsigned      g_cofs[NCELL + 1];
__device__ unsigned      g_ccur[NCELL];
__device__ unsigned      g_tcnt[NCELL];      // target grid counts
__device__ unsigned      g_tofs[NCELL + 1];
__device__ unsigned      g_tcur[NCELL];
__device__ float4        g_candS[LMAX];      // grid-sorted kept candidates
__device__ float4        g_tgtS[NMAX];       // grid-sorted targets
__device__ float         g_num[LMAX * 3];
__device__ float         g_den[LMAX];
__device__ int           g_exact[LMAX];
__device__ float         g_exrgb[LMAX * 3];
__device__ float4        g_eC[LMAX];         // compacted empty cands: x,y,z, bits(origIdx)
__device__ int           g_fwdidx[LMAX];     // per empty cand: chosen target idx

// ---------------- helpers ----------------
__device__ __forceinline__ unsigned f2u(float f) {
    unsigned i = __float_as_uint(f);
    return (i & 0x80000000u) ? ~i : (i | 0x80000000u);
}
__device__ __forceinline__ float u2f(unsigned u) {
    unsigned i = (u & 0x80000000u) ? (u & 0x7FFFFFFFu) : ~u;
    return __uint_as_float(i);
}
__device__ __forceinline__ ull umin64(ull a, ull b) { return a < b ? a : b; }

__device__ __forceinline__ int cellcoord(float v) {
    int i = (int)floorf((v - GORIG) * (1.0f / CELLW));
    return i < 0 ? 0 : (i > GRIDC - 1 ? GRIDC - 1 : i);
}

__device__ __forceinline__ float blockReduceSum(float v) {
    __shared__ float sh[32];
    int lane = threadIdx.x & 31, w = threadIdx.x >> 5;
#pragma unroll
    for (int o = 16; o > 0; o >>= 1) v += __shfl_down_sync(0xFFFFFFFFu, v, o);
    if (lane == 0) sh[w] = v;
    __syncthreads();
    v = (threadIdx.x < (blockDim.x >> 5)) ? sh[lane] : 0.f;
    if (w == 0) {
#pragma unroll
        for (int o = 16; o > 0; o >>= 1) v += __shfl_down_sync(0xFFFFFFFFu, v, o);
    }
    return v;
}

// warp-cooperative exact NN over a uniform grid. Returns packed (f2u(d2)<<32)|idx,
// identical on all lanes. Tie-break: smallest d2 bits, then smallest original idx.
__device__ ull nn_search(float px, float py, float pz,
                         const unsigned* __restrict__ ofs,
                         const float4* __restrict__ pts, int lane) {
    int cx = cellcoord(px), cy = cellcoord(py), cz = cellcoord(pz);
    ull best = 0xFFFFFFFFFFFFFFFFULL;
    for (int r = 0; r <= GRIDC; r++) {
        if (r > 0) {
            // all unscanned candidates lie outside box(r-1): distance >= m
            float bxlo = (cx - (r - 1)) * CELLW + GORIG;
            float bxhi = (cx + r) * CELLW + GORIG;
            float bylo = (cy - (r - 1)) * CELLW + GORIG;
            float byhi = (cy + r) * CELLW + GORIG;
            float bzlo = (cz - (r - 1)) * CELLW + GORIG;
            float bzhi = (cz + r) * CELLW + GORIG;
            float m = fminf(fminf(px - bxlo, bxhi - px),
                     fminf(fminf(py - bylo, byhi - py),
                           fminf(pz - bzlo, bzhi - pz)));
            float bd2 = u2f((unsigned)(best >> 32));
            if (bd2 < m * m) break;   // strict: equal-distance ties must still be scanned
        }
        int cnt = 0;
        int z0 = max(-r, -cz), z1 = min(r, GRIDC - 1 - cz);
        for (int dz = z0; dz <= z1; dz++) {
            int zc = cz + dz;
            int y0 = max(-r, -cy), y1 = min(r, GRIDC - 1 - cy);
            for (int dy = y0; dy <= y1; dy++) {
                int yc = cy + dy;
                bool edge = (dz == -r) || (dz == r) || (dy == -r) || (dy == r);
#define NN_VISIT(XC)                                                              \
                do {                                                              \
                    if (((cnt++) & 31) == lane) {                                 \
                        int cell = (zc * GRIDC + yc) * GRIDC + (XC);              \
                        unsigned s0 = ofs[cell], s1 = ofs[cell + 1];              \
                        for (unsigned j = s0; j < s1; j++) {                      \
                            float4 q = pts[j];                                    \
                            float ddx = q.x - px, ddy = q.y - py, ddz = q.z - pz; \
                            float d2 = fmaf(ddx, ddx, fmaf(ddy, ddy, ddz * ddz)); \
                            ull pk = ((ull)f2u(d2) << 32) | __float_as_uint(q.w); \
                            best = umin64(best, pk);                              \
                        }                                                         \
                    }                                                             \
                } while (0)
                if (edge) {
                    int x0 = max(-r, -cx), x1 = min(r, GRIDC - 1 - cx);
                    for (int dx = x0; dx <= x1; dx++) NN_VISIT(cx + dx);
                } else {
                    if (cx - r >= 0)        NN_VISIT(cx - r);
                    if (cx + r <= GRIDC - 1) NN_VISIT(cx + r);
                }
#undef NN_VISIT
            }
        }
#pragma unroll
        for (int o = 16; o > 0; o >>= 1)
            best = umin64(best, __shfl_xor_sync(0xFFFFFFFFu, best, o));
    }
    return best;
}

// ---------------- kernels ----------------
// zero scratch + local-max over groups of 8 + sortable keys
__global__ void k_initprep(const float* __restrict__ pred, float* out, int L, int N) {
    int i = blockIdx.x * blockDim.x + threadIdx.x;
    if (i == 0) { g_count = 0; g_ecount = 0; out[0] = 0.f; out[1] = 0.f; }
    if (i < NCELL) { g_ccnt[i] = 0u; g_tcnt[i] = 0u; }
    if (i < L) {
        g_num[3 * i] = 0.f; g_num[3 * i + 1] = 0.f; g_num[3 * i + 2] = 0.f;
        g_den[i] = 0.f; g_exact[i] = 0;
    }
    int G = L >> 3;
    if (i < G) {
        const float* p = pred + i * 8;
        float bv = p[0]; int bi = 0;
#pragma unroll
        for (int j = 1; j < 8; j++) { float v = p[j]; if (v > bv) { bv = v; bi = j; } }
#pragma unroll
        for (int j = 0; j < 8; j++) {
            bool lm = (j == bi);
            g_islm[i * 8 + j] = lm ? 1 : 0;
            g_keys[i * 8 + j] = f2u(lm ? POSINF : p[j]);
        }
    }
}

// single-block MSD radix select: threshold = k-th smallest of keys, k = L - points_num
__global__ void k_select(const int* __restrict__ pn, int L) {
    __shared__ unsigned hist[256];
    __shared__ unsigned s_prefix;
    __shared__ int s_rank;
    int tid = threadIdx.x;
    if (tid == 0) { s_prefix = 0u; s_rank = L - pn[0]; }
    __syncthreads();
    for (int round = 0; round < 4; round++) {
        int shift = 24 - 8 * round;
        if (tid < 256) hist[tid] = 0u;
        __syncthreads();
        unsigned pref = s_prefix;
        unsigned mask = (round == 0) ? 0u : (0xFFFFFFFFu << (shift + 8));
        for (int i = tid; i < L; i += blockDim.x) {
            unsigned u = g_keys[i];
            if ((u & mask) == pref) atomicAdd(&hist[(u >> shift) & 0xFFu], 1u);
        }
        __syncthreads();
        if (tid == 0) {
            int r = s_rank; unsigned b = 0;
            while (b < 256u) { int c = (int)hist[b]; if (c >= r) break; r -= c; b++; }
            s_rank = r;
            s_prefix = pref | (b << shift);
        }
        __syncthreads();
    }
    if (tid == 0) g_thr = u2f(s_prefix);
}

// keep mask, BCE, compaction, + grid cell counting for kept cands AND targets
__global__ void k_keep(const float* __restrict__ pred, const int* __restrict__ kt,
                       const float* __restrict__ cxyz, const float* __restrict__ txyz,
                       int L, int N, float* out) {
    int i = blockIdx.x * blockDim.x + threadIdx.x;
    float bce = 0.f; bool keep = false;
    float thr = g_thr;
    if (i < L) {
        float p = pred[i];
        float t = (float)kt[i];
        bce = fmaxf(p, 0.f) - p * t + log1pf(expf(-fabsf(p)));
        keep = (p > thr) || (g_islm[i] != 0);
    }
    unsigned m = __ballot_sync(0xFFFFFFFFu, keep);
    if (keep) {
        int lane = threadIdx.x & 31;
        int leader = __ffs(m) - 1;
        int base = 0;
        if (lane == leader) base = atomicAdd(&g_count, __popc(m));
        base = __shfl_sync(m, base, leader);
        int pos = base + __popc(m & ((1u << lane) - 1u));
        float x = cxyz[3 * i], y = cxyz[3 * i + 1], z = cxyz[3 * i + 2];
        g_candC[pos] = make_float4(x, y, z, __int_as_float(i));
        g_candIdx[pos] = i;
        int cell = (cellcoord(z) * GRIDC + cellcoord(y)) * GRIDC + cellcoord(x);
        atomicAdd(&g_ccnt[cell], 1u);
    }
    if (i < N) {
        float x = txyz[3 * i], y = txyz[3 * i + 1], z = txyz[3 * i + 2];
        int cell = (cellcoord(z) * GRIDC + cellcoord(y)) * GRIDC + cellcoord(x);
        atomicAdd(&g_tcnt[cell], 1u);
    }
    float s = blockReduceSum(bce);
    if (threadIdx.x == 0) atomicAdd(out, s);
}

// exclusive scan of the two 32768-cell count arrays (block 0: cand, block 1: tgt)
__global__ void k_scan() {
    __shared__ unsigned sw[32];
    const unsigned* cnt = blockIdx.x ? g_tcnt : g_ccnt;
    unsigned* ofs = blockIdx.x ? g_tofs : g_cofs;
    unsigned* cur = blockIdx.x ? g_tcur : g_ccur;
    int tid = threadIdx.x;           // 1024 threads, 32 cells each
    int base = tid * 32;
    unsigned v[32]; unsigned s = 0;
#pragma unroll
    for (int k = 0; k < 32; k++) { v[k] = s; s += cnt[base + k]; }
    unsigned lane = tid & 31, w = tid >> 5;
    unsigned x = s;
#pragma unroll
    for (int o = 1; o < 32; o <<= 1) {
        unsigned y = __shfl_up_sync(0xFFFFFFFFu, x, o);
        if (lane >= o) x += y;
    }
    if (lane == 31) sw[w] = x;
    __syncthreads();
    if (w == 0) {
        unsigned y = sw[lane];
#pragma unroll
        for (int o = 1; o < 32; o <<= 1) {
            unsigned z = __shfl_up_sync(0xFFFFFFFFu, y, o);
            if (lane >= o) y += z;
        }
        sw[lane] = y;
    }
    __syncthreads();
    unsigned boff = (w ? sw[w - 1] : 0u) + (x - s);
#pragma unroll
    for (int k = 0; k < 32; k++) { ofs[base + k] = boff + v[k]; cur[base + k] = boff + v[k]; }
    if (tid == 1023) ofs[NCELL] = boff + s;
}

// scatter kept candidates and targets into grid-sorted arrays
__global__ void k_scat(const float* __restrict__ txyz, int N) {
    int i = blockIdx.x * blockDim.x + threadIdx.x;
    if (i < g_count) {
        float4 c = g_candC[i];
        int cell = (cellcoord(c.z) * GRIDC + cellcoord(c.y)) * GRIDC + cellcoord(c.x);
        unsigned pos = atomicAdd(&g_ccur[cell], 1u);
        g_candS[pos] = c;
    }
    if (i < N) {
        float x = txyz[3 * i], y = txyz[3 * i + 1], z = txyz[3 * i + 2];
        int cell = (cellcoord(z) * GRIDC + cellcoord(y)) * GRIDC + cellcoord(x);
        unsigned pos = atomicAdd(&g_tcur[cell], 1u);
        g_tgtS[pos] = make_float4(x, y, z, __int_as_float(i));
    }
}

// backward: one warp per target; exact NN over kept-candidate grid; scatter color
__global__ void __launch_bounds__(128) k_bwdnn(const float* __restrict__ txyz,
                                               const float* __restrict__ trgb, int N) {
    int gw = (blockIdx.x * blockDim.x + threadIdx.x) >> 5;
    if (gw >= N) return;
    int lane = threadIdx.x & 31;
    float px = txyz[3 * gw], py = txyz[3 * gw + 1], pz = txyz[3 * gw + 2];
    ull best = nn_search(px, py, pz, g_cofs, g_candS, lane);
    if (lane == 0) {
        float d2 = u2f((unsigned)(best >> 32));
        int idx = (int)(unsigned)(best & 0xFFFFFFFFULL);
        float r = trgb[3 * gw], g = trgb[3 * gw + 1], b = trgb[3 * gw + 2];
        if (d2 == 0.f) {
            g_exact[idx] = 1;
            g_exrgb[3 * idx] = r; g_exrgb[3 * idx + 1] = g; g_exrgb[3 * idx + 2] = b;
        } else {
            float w = 1.0f / sqrtf(fmaxf(d2, 1e-30f));
            atomicAdd(&g_num[3 * idx],     r * w);
            atomicAdd(&g_num[3 * idx + 1], g * w);
            atomicAdd(&g_num[3 * idx + 2], b * w);
            atomicAdd(&g_den[idx], w);
        }
    }
}

// compact kept candidates that received no color (the "empty" set)
__global__ void k_compactE(int L) {
    int p = blockIdx.x * blockDim.x + threadIdx.x;
    bool e = false; int l = 0;
    float x = 0.f, y = 0.f, z = 0.f;
    if (p < g_count) {
        l = g_candIdx[p];
        if (g_den[l] == 0.f && g_exact[l] == 0) {
            e = true;
            float4 c = g_candC[p];
            x = c.x; y = c.y; z = c.z;
        }
    }
    unsigned m = __ballot_sync(0xFFFFFFFFu, e);
    if (e) {
        int lane = threadIdx.x & 31;
        int leader = __ffs(m) - 1;
        int base = 0;
        if (lane == leader) base = atomicAdd(&g_ecount, __popc(m));
        base = __shfl_sync(m, base, leader);
        int pos = base + __popc(m & ((1u << lane) - 1u));
        g_eC[pos] = make_float4(x, y, z, __int_as_float(l));
    }
}

// forward: one warp per empty candidate; exact NN over target grid
__global__ void __launch_bounds__(128) k_fwdnn() {
    int gw = (blockIdx.x * blockDim.x + threadIdx.x) >> 5;
    if (gw >= g_ecount) return;
    int lane = threadIdx.x & 31;
    float4 c = g_eC[gw];
    ull best = nn_search(c.x, c.y, c.z, g_tofs, g_tgtS, lane);
    if (lane == 0) {
        int l = __float_as_int(c.w);
        g_fwdidx[l] = (int)(unsigned)(best & 0xFFFFFFFFULL);
    }
}

// final L1 loss over kept candidates
__global__ void k_final(const float* __restrict__ crgb, const float* __restrict__ trgb,
                        float* out, int N) {
    int p = blockIdx.x * blockDim.x + threadIdx.x;
    float loss = 0.f;
    if (p < g_count) {
        int l = g_candIdx[p];
        float r0, r1, r2;
        if (g_exact[l]) {
            r0 = g_exrgb[3 * l]; r1 = g_exrgb[3 * l + 1]; r2 = g_exrgb[3 * l + 2];
        } else {
            float den = g_den[l];
            if (den != 0.f) {
                r0 = g_num[3 * l] / den;
                r1 = g_num[3 * l + 1] / den;
                r2 = g_num[3 * l + 2] / den;
            } else {
                int ti = g_fwdidx[l];
                r0 = trgb[3 * ti]; r1 = trgb[3 * ti + 1]; r2 = trgb[3 * ti + 2];
            }
        }
        float q0 = crgb[3 * l] * 255.f;
        float q1 = crgb[3 * l + 1] * 255.f;
        float q2 = crgb[3 * l + 2] * 255.f;
        loss = fabsf(q0 - r0) + fabsf(q1 - r1) + fabsf(q2 - r2);
    }
    float s = blockReduceSum(loss);
    if (threadIdx.x == 0) atomicAdd(out + 1, s);
}

// ---------------- launch ----------------
extern "C" void kernel_launch(void* const* d_in, const int* in_sizes, int n_in,
                              void* d_out, int out_size) {
    const float* pred = (const float*)d_in[0];
    const float* cxyz = (const float*)d_in[1];
    const float* crgb = (const float*)d_in[2];
    const float* txyz = (const float*)d_in[3];
    const float* trgb = (const float*)d_in[4];
    const int*   kt   = (const int*)d_in[5];
    const int*   pn   = (const int*)d_in[6];
    float* out = (float*)d_out;

    int L = in_sizes[0];
    int N = in_sizes[3] / 3;
    int M = L > N ? L : N;
    if (M < NCELL) M = NCELL;

    k_initprep<<<(M + 255) / 256, 256>>>(pred, out, L, N);
    k_select<<<1, 1024>>>(pn, L);
    int LN = L > N ? L : N;
    k_keep<<<(LN + 255) / 256, 256>>>(pred, kt, cxyz, txyz, L, N, out);
    k_scan<<<2, 1024>>>();
    k_scat<<<(LN + 255) / 256, 256>>>(txyz, N);
    k_bwdnn<<<(N * 32 + 127) / 128, 128>>>(txyz, trgb, N);
    k_compactE<<<(L + 255) / 256, 256>>>(L);
    k_fwdnn<<<(L * 32 + 127) / 128, 128>>>();
    k_final<<<(L + 255) / 256, 256>>>(crgb, trgb, out, N);
}

// round 9
// speedup vs baseline: 3.5805x; 3.5805x over previous
#include <cuda_runtime.h>

#define LMAX 32768
#define NMAX 32768
#define GRIDC 16
#define NCELL (GRIDC * GRIDC * GRIDC)
#define CELLW 32.0f
#define GORIG (-256.0f)

#define POSINF __int_as_float(0x7F800000)

typedef unsigned long long ull;

// ---------------- device scratch (no allocations allowed) ----------------
__device__ unsigned int  g_keys[LMAX];
__device__ unsigned char g_islm[LMAX];
__device__ float         g_thr;
__device__ int           g_count;
__device__ float4        g_candC[LMAX];      // kept cand: x,y,z, bits(origIdx)
__device__ int           g_candIdx[LMAX];    // compacted kept -> original index
__device__ unsigned      g_ccnt[NCELL];      // candidate grid counts
__device__ unsigned      g_cofs[NCELL + 1];
__device__ unsigned      g_ccur[NCELL];
__device__ unsigned      g_tcnt[NCELL];      // target grid counts
__device__ unsigned      g_tofs[NCELL + 1];
__device__ unsigned      g_tcur[NCELL];
__device__ float4        g_candS[LMAX];      // grid-sorted kept candidates
__device__ float4        g_tgtS[NMAX];       // grid-sorted targets
__device__ float         g_num[LMAX * 3];
__device__ float         g_den[LMAX];
__device__ int           g_exact[LMAX];
__device__ float         g_exrgb[LMAX * 3];
__device__ int           g_fwdidx[LMAX];     // per empty cand: chosen target idx

// ---------------- helpers ----------------
__device__ __forceinline__ unsigned f2u(float f) {
    unsigned i = __float_as_uint(f);
    return (i & 0x80000000u) ? ~i : (i | 0x80000000u);
}
__device__ __forceinline__ float u2f(unsigned u) {
    unsigned i = (u & 0x80000000u) ? (u & 0x7FFFFFFFu) : ~u;
    return __uint_as_float(i);
}
__device__ __forceinline__ ull umin64(ull a, ull b) { return a < b ? a : b; }

__device__ __forceinline__ int cellcoord(float v) {
    int i = (int)floorf((v - GORIG) * (1.0f / CELLW));
    return i < 0 ? 0 : (i > GRIDC - 1 ? GRIDC - 1 : i);
}

__device__ __forceinline__ float blockReduceSum(float v) {
    __shared__ float sh[32];
    int lane = threadIdx.x & 31, w = threadIdx.x >> 5;
#pragma unroll
    for (int o = 16; o > 0; o >>= 1) v += __shfl_down_sync(0xFFFFFFFFu, v, o);
    if (lane == 0) sh[w] = v;
    __syncthreads();
    v = (threadIdx.x < (blockDim.x >> 5)) ? sh[lane] : 0.f;
    if (w == 0) {
#pragma unroll
        for (int o = 16; o > 0; o >>= 1) v += __shfl_down_sync(0xFFFFFFFFu, v, o);
    }
    return v;
}

__device__ __forceinline__ ull warpMin64(ull best) {
#pragma unroll
    for (int o = 16; o > 0; o >>= 1)
        best = umin64(best, __shfl_xor_sync(0xFFFFFFFFu, best, o));
    return best;
}

// warp-cooperative exact NN: warp walks cells serially, lanes take consecutive
// list elements (coalesced). Returns packed (f2u(d2)<<32)|idx on all lanes.
// Tie-break: smallest d2 bits then smallest idx (strict bound keeps ties scanned).
__device__ ull nn_search(float px, float py, float pz,
                         const unsigned* __restrict__ ofs,
                         const float4* __restrict__ pts, int lane) {
    int cx = cellcoord(px), cy = cellcoord(py), cz = cellcoord(pz);
    ull best = 0xFFFFFFFFFFFFFFFFULL;

#define NN_CELL(ZC, YC, XC)                                                   \
    do {                                                                      \
        int cell_ = ((ZC) * GRIDC + (YC)) * GRIDC + (XC);                     \
        unsigned s0_ = ofs[cell_], s1_ = ofs[cell_ + 1];                      \
        for (unsigned j = s0_ + lane; j < s1_; j += 32) {                     \
            float4 q = pts[j];                                                \
            float ddx = q.x - px, ddy = q.y - py, ddz = q.z - pz;             \
            float d2 = fmaf(ddx, ddx, fmaf(ddy, ddy, ddz * ddz));             \
            ull pk = ((ull)f2u(d2) << 32) | __float_as_uint(q.w);             \
            best = umin64(best, pk);                                          \
        }                                                                     \
    } while (0)

    // Phase A: clipped 3x3x3 neighborhood
    {
        int zlo = max(cz - 1, 0), zhi = min(cz + 1, GRIDC - 1);
        int ylo = max(cy - 1, 0), yhi = min(cy + 1, GRIDC - 1);
        int xlo = max(cx - 1, 0), xhi = min(cx + 1, GRIDC - 1);
        for (int zc = zlo; zc <= zhi; zc++)
            for (int yc = ylo; yc <= yhi; yc++)
                for (int xc = xlo; xc <= xhi; xc++)
                    NN_CELL(zc, yc, xc);
        best = warpMin64(best);
        float m = fminf(fminf(px - ((cx - 1) * CELLW + GORIG), ((cx + 2) * CELLW + GORIG) - px),
                 fminf(fminf(py - ((cy - 1) * CELLW + GORIG), ((cy + 2) * CELLW + GORIG) - py),
                       fminf(pz - ((cz - 1) * CELLW + GORIG), ((cz + 2) * CELLW + GORIG) - pz)));
        float bd2 = u2f((unsigned)(best >> 32));
        if (bd2 < m * m) return best;   // strict: ties keep scanning
    }

    // Phase B: rings r >= 2 (rare)
    for (int r = 2; r <= GRIDC; r++) {
        int z0 = max(-r, -cz), z1 = min(r, GRIDC - 1 - cz);
        for (int dz = z0; dz <= z1; dz++) {
            int zc = cz + dz;
            int y0 = max(-r, -cy), y1 = min(r, GRIDC - 1 - cy);
            for (int dy = y0; dy <= y1; dy++) {
                int yc = cy + dy;
                bool edge = (dz == -r) || (dz == r) || (dy == -r) || (dy == r);
                if (edge) {
                    int x0 = max(-r, -cx), x1 = min(r, GRIDC - 1 - cx);
                    for (int dx = x0; dx <= x1; dx++) NN_CELL(zc, yc, cx + dx);
                } else {
                    if (cx - r >= 0)         NN_CELL(zc, yc, cx - r);
                    if (cx + r <= GRIDC - 1) NN_CELL(zc, yc, cx + r);
                }
            }
        }
        best = warpMin64(best);
        float m = fminf(fminf(px - ((cx - r) * CELLW + GORIG), ((cx + r + 1) * CELLW + GORIG) - px),
                 fminf(fminf(py - ((cy - r) * CELLW + GORIG), ((cy + r + 1) * CELLW + GORIG) - py),
                       fminf(pz - ((cz - r) * CELLW + GORIG), ((cz + r + 1) * CELLW + GORIG) - pz)));
        float bd2 = u2f((unsigned)(best >> 32));
        if (bd2 < m * m) break;
    }
#undef NN_CELL
    return best;
}

// ---------------- kernels ----------------
// zero scratch + local-max over groups of 8 + sortable keys
__global__ void k_initprep(const float* __restrict__ pred, float* out, int L) {
    int i = blockIdx.x * blockDim.x + threadIdx.x;
    if (i == 0) { g_count = 0; out[0] = 0.f; out[1] = 0.f; }
    if (i < NCELL) { g_ccnt[i] = 0u; g_tcnt[i] = 0u; }
    if (i < L) {
        g_num[3 * i] = 0.f; g_num[3 * i + 1] = 0.f; g_num[3 * i + 2] = 0.f;
        g_den[i] = 0.f; g_exact[i] = 0;
    }
    int G = L >> 3;
    if (i < G) {
        const float* p = pred + i * 8;
        float bv = p[0]; int bi = 0;
#pragma unroll
        for (int j = 1; j < 8; j++) { float v = p[j]; if (v > bv) { bv = v; bi = j; } }
#pragma unroll
        for (int j = 0; j < 8; j++) {
            bool lm = (j == bi);
            g_islm[i * 8 + j] = lm ? 1 : 0;
            g_keys[i * 8 + j] = f2u(lm ? POSINF : p[j]);
        }
    }
}

// single-block MSD radix select: threshold = k-th smallest of keys, k = L - points_num
__global__ void k_select(const int* __restrict__ pn, int L) {
    __shared__ unsigned hist[256];
    __shared__ unsigned s_prefix;
    __shared__ int s_rank;
    int tid = threadIdx.x;
    if (tid == 0) { s_prefix = 0u; s_rank = L - pn[0]; }
    __syncthreads();
    for (int round = 0; round < 4; round++) {
        int shift = 24 - 8 * round;
        if (tid < 256) hist[tid] = 0u;
        __syncthreads();
        unsigned pref = s_prefix;
        unsigned mask = (round == 0) ? 0u : (0xFFFFFFFFu << (shift + 8));
        for (int i = tid; i < L; i += blockDim.x) {
            unsigned u = g_keys[i];
            if ((u & mask) == pref) atomicAdd(&hist[(u >> shift) & 0xFFu], 1u);
        }
        __syncthreads();
        if (tid == 0) {
            int r = s_rank; unsigned b = 0;
            while (b < 256u) { int c = (int)hist[b]; if (c >= r) break; r -= c; b++; }
            s_rank = r;
            s_prefix = pref | (b << shift);
        }
        __syncthreads();
    }
    if (tid == 0) g_thr = u2f(s_prefix);
}

// keep mask, BCE, compaction, + grid cell counting for kept cands AND targets
__global__ void k_keep(const float* __restrict__ pred, const int* __restrict__ kt,
                       const float* __restrict__ cxyz, const float* __restrict__ txyz,
                       int L, int N, float* out) {
    int i = blockIdx.x * blockDim.x + threadIdx.x;
    float bce = 0.f; bool keep = false;
    float thr = g_thr;
    if (i < L) {
        float p = pred[i];
        float t = (float)kt[i];
        bce = fmaxf(p, 0.f) - p * t + log1pf(expf(-fabsf(p)));
        keep = (p > thr) || (g_islm[i] != 0);
    }
    unsigned m = __ballot_sync(0xFFFFFFFFu, keep);
    if (keep) {
        int lane = threadIdx.x & 31;
        int leader = __ffs(m) - 1;
        int base = 0;
        if (lane == leader) base = atomicAdd(&g_count, __popc(m));
        base = __shfl_sync(m, base, leader);
        int pos = base + __popc(m & ((1u << lane) - 1u));
        float x = cxyz[3 * i], y = cxyz[3 * i + 1], z = cxyz[3 * i + 2];
        g_candC[pos] = make_float4(x, y, z, __int_as_float(i));
        g_candIdx[pos] = i;
        int cell = (cellcoord(z) * GRIDC + cellcoord(y)) * GRIDC + cellcoord(x);
        atomicAdd(&g_ccnt[cell], 1u);
    }
    if (i < N) {
        float x = txyz[3 * i], y = txyz[3 * i + 1], z = txyz[3 * i + 2];
        int cell = (cellcoord(z) * GRIDC + cellcoord(y)) * GRIDC + cellcoord(x);
        atomicAdd(&g_tcnt[cell], 1u);
    }
    float s = blockReduceSum(bce);
    if (threadIdx.x == 0) atomicAdd(out, s);
}

// exclusive scan of both 4096-cell count arrays; single block, coalesced rounds
__global__ void k_scan() {
    __shared__ unsigned sw[32];
    __shared__ unsigned s_carry;
    int tid = threadIdx.x;
    int lane = tid & 31, w = tid >> 5;
#pragma unroll
    for (int a = 0; a < 2; a++) {
        const unsigned* cnt = a ? g_tcnt : g_ccnt;
        unsigned* ofs = a ? g_tofs : g_cofs;
        unsigned* cur = a ? g_tcur : g_ccur;
        if (tid == 0) s_carry = 0u;
        __syncthreads();
        for (int base = 0; base < NCELL; base += 1024) {
            unsigned v = cnt[base + tid];
            unsigned x = v;
#pragma unroll
            for (int o = 1; o < 32; o <<= 1) {
                unsigned y = __shfl_up_sync(0xFFFFFFFFu, x, o);
                if (lane >= o) x += y;
            }
            if (lane == 31) sw[w] = x;
            __syncthreads();
            if (w == 0) {
                unsigned y = sw[lane];
#pragma unroll
                for (int o = 1; o < 32; o <<= 1) {
                    unsigned z = __shfl_up_sync(0xFFFFFFFFu, y, o);
                    if (lane >= o) y += z;
                }
                sw[lane] = y;
            }
            __syncthreads();
            unsigned off = s_carry + (w ? sw[w - 1] : 0u) + (x - v);
            ofs[base + tid] = off;
            cur[base + tid] = off;
            __syncthreads();
            if (tid == 0) s_carry += sw[31];
            __syncthreads();
        }
        if (tid == 0) ofs[NCELL] = s_carry;
        __syncthreads();
    }
}

// scatter kept candidates and targets into grid-sorted arrays
__global__ void k_scat(const float* __restrict__ txyz, int N) {
    int i = blockIdx.x * blockDim.x + threadIdx.x;
    if (i < g_count) {
        float4 c = g_candC[i];
        int cell = (cellcoord(c.z) * GRIDC + cellcoord(c.y)) * GRIDC + cellcoord(c.x);
        unsigned pos = atomicAdd(&g_ccur[cell], 1u);
        g_candS[pos] = c;
    }
    if (i < N) {
        float x = txyz[3 * i], y = txyz[3 * i + 1], z = txyz[3 * i + 2];
        int cell = (cellcoord(z) * GRIDC + cellcoord(y)) * GRIDC + cellcoord(x);
        unsigned pos = atomicAdd(&g_tcur[cell], 1u);
        g_tgtS[pos] = make_float4(x, y, z, __int_as_float(i));
    }
}

// backward: one warp per target (cell-sorted order for locality); exact NN over
// kept-candidate grid; scatter weighted color from lane 0.
__global__ void __launch_bounds__(256) k_bwdnn(const float* __restrict__ trgb, int N) {
    int gw = (blockIdx.x * blockDim.x + threadIdx.x) >> 5;
    if (gw >= N) return;
    int lane = threadIdx.x & 31;
    float4 t = g_tgtS[gw];
    ull best = nn_search(t.x, t.y, t.z, g_cofs, g_candS, lane);
    if (lane == 0) {
        int ti = __float_as_int(t.w);
        float d2 = u2f((unsigned)(best >> 32));
        int idx = (int)(unsigned)(best & 0xFFFFFFFFULL);
        float r = trgb[3 * ti], g = trgb[3 * ti + 1], b = trgb[3 * ti + 2];
        if (d2 == 0.f) {
            g_exact[idx] = 1;
            g_exrgb[3 * idx] = r; g_exrgb[3 * idx + 1] = g; g_exrgb[3 * idx + 2] = b;
        } else {
            float w = 1.0f / sqrtf(fmaxf(d2, 1e-30f));
            atomicAdd(&g_num[3 * idx],     r * w);
            atomicAdd(&g_num[3 * idx + 1], g * w);
            atomicAdd(&g_num[3 * idx + 2], b * w);
            atomicAdd(&g_den[idx], w);
        }
    }
}

// forward: one warp per kept slot; inline empty check; exact NN over target grid
__global__ void __launch_bounds__(256) k_fwdnn() {
    int p = (blockIdx.x * blockDim.x + threadIdx.x) >> 5;
    if (p >= g_count) return;
    int l = g_candIdx[p];
    if (g_den[l] != 0.f || g_exact[l] != 0) return;   // not empty
    int lane = threadIdx.x & 31;
    float4 c = g_candC[p];
    ull best = nn_search(c.x, c.y, c.z, g_tofs, g_tgtS, lane);
    if (lane == 0) g_fwdidx[l] = (int)(unsigned)(best & 0xFFFFFFFFULL);
}

// final L1 loss over kept candidates
__global__ void k_final(const float* __restrict__ crgb, const float* __restrict__ trgb,
                        float* out, int N) {
    int p = blockIdx.x * blockDim.x + threadIdx.x;
    float loss = 0.f;
    if (p < g_count) {
        int l = g_candIdx[p];
        float r0, r1, r2;
        if (g_exact[l]) {
            r0 = g_exrgb[3 * l]; r1 = g_exrgb[3 * l + 1]; r2 = g_exrgb[3 * l + 2];
        } else {
            float den = g_den[l];
            if (den != 0.f) {
                r0 = g_num[3 * l] / den;
                r1 = g_num[3 * l + 1] / den;
                r2 = g_num[3 * l + 2] / den;
            } else {
                int ti = g_fwdidx[l];
                r0 = trgb[3 * ti]; r1 = trgb[3 * ti + 1]; r2 = trgb[3 * ti + 2];
            }
        }
        float q0 = crgb[3 * l] * 255.f;
        float q1 = crgb[3 * l + 1] * 255.f;
        float q2 = crgb[3 * l + 2] * 255.f;
        loss = fabsf(q0 - r0) + fabsf(q1 - r1) + fabsf(q2 - r2);
    }
    float s = blockReduceSum(loss);
    if (threadIdx.x == 0) atomicAdd(out + 1, s);
}

// ---------------- launch ----------------
extern "C" void kernel_launch(void* const* d_in, const int* in_sizes, int n_in,
                              void* d_out, int out_size) {
    const float* pred = (const float*)d_in[0];
    const float* cxyz = (const float*)d_in[1];
    const float* crgb = (const float*)d_in[2];
    const float* txyz = (const float*)d_in[3];
    const float* trgb = (const float*)d_in[4];
    const int*   kt   = (const int*)d_in[5];
    const int*   pn   = (const int*)d_in[6];
    float* out = (float*)d_out;

    int L = in_sizes[0];
    int N = in_sizes[3] / 3;
    int LN = L > N ? L : N;
    int M = LN > NCELL ? LN : NCELL;

    k_initprep<<<(M + 255) / 256, 256>>>(pred, out, L);
    k_select<<<1, 1024>>>(pn, L);
    k_keep<<<(LN + 255) / 256, 256>>>(pred, kt, cxyz, txyz, L, N, out);
    k_scan<<<1, 1024>>>();
    k_scat<<<(LN + 255) / 256, 256>>>(txyz, N);
    k_bwdnn<<<(N * 32 + 255) / 256, 256>>>(trgb, N);
    k_fwdnn<<<((long long)L * 32 + 255) / 256, 256>>>();
    k_final<<<(L + 255) / 256, 256>>>(crgb, trgb, out, N);
}